// round 2
// baseline (speedup 1.0000x reference)
#include <cuda_runtime.h>
#include <cuda_bf16.h>

// Problem constants
#define NMAX   50000
#define EMAX   800000
#define NF     128      // IN_F
#define HH     256      // HEADS*HID
#define OUT2   128      // OUT
#define NHEADS 4
#define HID    64
#define NEG    0.2f

// ---- scratch (static device globals; no allocation allowed) ----
__device__ float g_h1  [(size_t)NMAX * HH];   // layer1 per-node features
__device__ float g_agg1[(size_t)NMAX * HH];   // layer1 aggregated output
__device__ float g_h2  [(size_t)NMAX * OUT2]; // layer2 per-node features
__device__ float g_as1[NMAX * NHEADS];
__device__ float g_ad1[NMAX * NHEADS];
__device__ float g_den1[NMAX * NHEADS];
__device__ float g_as2[NMAX];
__device__ float g_ad2[NMAX];
__device__ float g_den2[NMAX];
__device__ int   g_is64;                      // 1 if edge_index is int64

__device__ __forceinline__ float warp_sum(float v) {
    #pragma unroll
    for (int o = 16; o > 0; o >>= 1) v += __shfl_xor_sync(0xffffffffu, v, o);
    return v;
}

// Edge accessor handling int32 vs int64 edge_index (row 0 = src, row 1 = dst).
__device__ __forceinline__ void load_edge(const void* ei, int E, int i,
                                          int& s, int& d) {
    if (g_is64) {
        const long long* p = (const long long*)ei;
        s = (int)p[i];
        d = (int)p[(size_t)E + i];
    } else {
        const int* p = (const int*)ei;
        s = p[i];
        d = p[E + i];
    }
}

// ============ K0: detect edge_index dtype ============
// View buffer as int32. If the underlying data is int64 (values < 2^31),
// every odd int32 is a zero high-word. If it's int32, odd positions hold
// random edge indices (~1/50000 chance of a single zero).
__global__ void k0_detect(const int* ei32, int E) {
    __shared__ int flag;
    if (threadIdx.x == 0) flag = 0;
    __syncthreads();
    for (int j = threadIdx.x; j < 2048; j += blockDim.x) {
        int idx = 2 * j + 1;
        if (idx < 2 * E && ei32[idx] != 0) flag = 1;   // benign race
    }
    __syncthreads();
    if (threadIdx.x == 0) g_is64 = (flag == 0);
}

// ============ K1: h1 = x @ W1   (50000x128 @ 128x256) ============
__global__ void k1_gemm1(const float* __restrict__ x, const float* __restrict__ W1,
                         int n_nodes) {
    __shared__ float xs[16][NF];
    const int n0 = blockIdx.x * 16;
    const int tid = threadIdx.x;
    for (int i = tid; i < 16 * NF; i += 256) {
        int nn = i >> 7, k = i & 127;
        int g = n0 + nn;
        xs[nn][k] = (g < n_nodes) ? x[(size_t)g * NF + k] : 0.f;
    }
    __syncthreads();
    const int tx = tid & 63, ty = tid >> 6;
    float acc[4][4] = {};
    #pragma unroll 4
    for (int k = 0; k < NF; k++) {
        float w0 = W1[k * HH + tx];
        float w1 = W1[k * HH + tx + 64];
        float w2 = W1[k * HH + tx + 128];
        float w3 = W1[k * HH + tx + 192];
        #pragma unroll
        for (int t = 0; t < 4; t++) {
            float a = xs[ty * 4 + t][k];
            acc[t][0] += a * w0; acc[t][1] += a * w1;
            acc[t][2] += a * w2; acc[t][3] += a * w3;
        }
    }
    #pragma unroll
    for (int t = 0; t < 4; t++) {
        int g = n0 + ty * 4 + t;
        if (g < n_nodes) {
            #pragma unroll
            for (int q = 0; q < 4; q++)
                g_h1[(size_t)g * HH + tx + 64 * q] = acc[t][q];
        }
    }
}

// ============ K1b: per-node attention logits + zero accumulators ============
__global__ void k1b_alpha1(const float* __restrict__ att_src,
                           const float* __restrict__ att_dst) {
    const int n = blockIdx.x;
    const int j = threadIdx.x;        // 256
    float v = g_h1[(size_t)n * HH + j];
    g_agg1[(size_t)n * HH + j] = 0.f;
    float sv = warp_sum(v * att_src[j]);
    float dv = warp_sum(v * att_dst[j]);
    __shared__ float rs[8], rd[8];
    int w = j >> 5, lane = j & 31;
    if (lane == 0) { rs[w] = sv; rd[w] = dv; }
    __syncthreads();
    if (j < NHEADS) {
        g_as1[n * NHEADS + j] = rs[2 * j] + rs[2 * j + 1];
        g_ad1[n * NHEADS + j] = rd[2 * j] + rd[2 * j + 1];
        g_den1[n * NHEADS + j] = 0.f;
    }
}

// ============ K2: softmax denominators, layer 1 ============
__global__ void k2_den1(const void* __restrict__ ei, int E, int ET) {
    int i = blockIdx.x * blockDim.x + threadIdx.x;
    if (i >= ET) return;
    int s, d;
    if (i < E) load_edge(ei, E, i, s, d);
    else       s = d = i - E;
    #pragma unroll
    for (int h = 0; h < NHEADS; h++) {
        float v = g_as1[s * NHEADS + h] + g_ad1[d * NHEADS + h];
        v = v > 0.f ? v : NEG * v;
        atomicAdd(&g_den1[d * NHEADS + h], __expf(v));
    }
}

// ============ K3: weighted aggregation, layer 1 (warp/edge) ============
__global__ void k3_agg1(const void* __restrict__ ei, int E, int ET) {
    int w = blockIdx.x * 8 + (threadIdx.x >> 5);
    if (w >= ET) return;
    const int lane = threadIdx.x & 31;
    int s, d;
    if (w < E) load_edge(ei, E, w, s, d);
    else       s = d = w - E;
    float alpha[NHEADS];
    #pragma unroll
    for (int h = 0; h < NHEADS; h++) {
        float v = g_as1[s * NHEADS + h] + g_ad1[d * NHEADS + h];
        v = v > 0.f ? v : NEG * v;
        alpha[h] = __expf(v) / g_den1[d * NHEADS + h];
    }
    const float* hs = g_h1 + (size_t)s * HH;
    float* od = g_agg1 + (size_t)d * HH;
    #pragma unroll
    for (int i = 0; i < 2; i++) {
        int j = lane * 4 + 128 * i;      // 4-aligned, within one head group
        float4 hv = *reinterpret_cast<const float4*>(hs + j);
        float a = alpha[j >> 6];
        atomicAdd(od + j + 0, hv.x * a);
        atomicAdd(od + j + 1, hv.y * a);
        atomicAdd(od + j + 2, hv.z * a);
        atomicAdd(od + j + 3, hv.w * a);
    }
}

// ============ K4: h2 = elu(agg1 + b1) @ W2   (50000x256 @ 256x128) ============
__global__ void k4_gemm2(const float* __restrict__ W2, const float* __restrict__ b1,
                         int n_nodes) {
    __shared__ float xs[16][HH];     // 16 KB
    const int n0 = blockIdx.x * 16;
    const int tid = threadIdx.x;     // 128
    for (int i = tid; i < 16 * HH; i += 128) {
        int nn = i >> 8, k = i & 255;
        int g = n0 + nn;
        float v = 0.f;
        if (g < n_nodes) {
            v = g_agg1[(size_t)g * HH + k] + b1[k];
            v = v > 0.f ? v : expm1f(v);      // elu, alpha=1
        }
        xs[nn][k] = v;
    }
    __syncthreads();
    const int tx = tid & 31, ty = tid >> 5;
    float acc[4][4] = {};
    #pragma unroll 4
    for (int k = 0; k < HH; k++) {
        float w0 = W2[k * OUT2 + tx];
        float w1 = W2[k * OUT2 + tx + 32];
        float w2 = W2[k * OUT2 + tx + 64];
        float w3 = W2[k * OUT2 + tx + 96];
        #pragma unroll
        for (int t = 0; t < 4; t++) {
            float a = xs[ty * 4 + t][k];
            acc[t][0] += a * w0; acc[t][1] += a * w1;
            acc[t][2] += a * w2; acc[t][3] += a * w3;
        }
    }
    #pragma unroll
    for (int t = 0; t < 4; t++) {
        int g = n0 + ty * 4 + t;
        if (g < n_nodes) {
            #pragma unroll
            for (int q = 0; q < 4; q++)
                g_h2[(size_t)g * OUT2 + tx + 32 * q] = acc[t][q];
        }
    }
}

// ============ K4b: layer-2 logits, zero den2, init out with b2 ============
__global__ void k4b_alpha2(const float* __restrict__ att_src,
                           const float* __restrict__ att_dst,
                           const float* __restrict__ b2,
                           float* __restrict__ out) {
    const int n = blockIdx.x;
    const int j = threadIdx.x;   // 128
    float v = g_h2[(size_t)n * OUT2 + j];
    out[(size_t)n * OUT2 + j] = b2[j];
    float sv = warp_sum(v * att_src[j]);
    float dv = warp_sum(v * att_dst[j]);
    __shared__ float rs[4], rd[4];
    int w = j >> 5, lane = j & 31;
    if (lane == 0) { rs[w] = sv; rd[w] = dv; }
    __syncthreads();
    if (j == 0) {
        g_as2[n] = rs[0] + rs[1] + rs[2] + rs[3];
        g_ad2[n] = rd[0] + rd[1] + rd[2] + rd[3];
        g_den2[n] = 0.f;
    }
}

// ============ K5: softmax denominators, layer 2 ============
__global__ void k5_den2(const void* __restrict__ ei, int E, int ET) {
    int i = blockIdx.x * blockDim.x + threadIdx.x;
    if (i >= ET) return;
    int s, d;
    if (i < E) load_edge(ei, E, i, s, d);
    else       s = d = i - E;
    float v = g_as2[s] + g_ad2[d];
    v = v > 0.f ? v : NEG * v;
    atomicAdd(&g_den2[d], __expf(v));
}

// ============ K6: weighted aggregation, layer 2 (warp/edge) ============
__global__ void k6_agg2(const void* __restrict__ ei, int E, int ET,
                        float* __restrict__ out) {
    int w = blockIdx.x * 8 + (threadIdx.x >> 5);
    if (w >= ET) return;
    const int lane = threadIdx.x & 31;
    int s, d;
    if (w < E) load_edge(ei, E, w, s, d);
    else       s = d = w - E;
    float v = g_as2[s] + g_ad2[d];
    v = v > 0.f ? v : NEG * v;
    float alpha = __expf(v) / g_den2[d];
    const float* hs = g_h2 + (size_t)s * OUT2;
    float* od = out + (size_t)d * OUT2;
    int j = lane * 4;
    float4 hv = *reinterpret_cast<const float4*>(hs + j);
    atomicAdd(od + j + 0, hv.x * alpha);
    atomicAdd(od + j + 1, hv.y * alpha);
    atomicAdd(od + j + 2, hv.z * alpha);
    atomicAdd(od + j + 3, hv.w * alpha);
}

extern "C" void kernel_launch(void* const* d_in, const int* in_sizes, int n_in,
                              void* d_out, int out_size) {
    const float* x    = (const float*)d_in[0];
    const void*  ei   = d_in[1];
    const float* W1   = (const float*)d_in[2];
    const float* as1  = (const float*)d_in[3];
    const float* ad1  = (const float*)d_in[4];
    const float* b1   = (const float*)d_in[5];
    const float* W2   = (const float*)d_in[6];
    const float* as2  = (const float*)d_in[7];
    const float* ad2  = (const float*)d_in[8];
    const float* b2   = (const float*)d_in[9];
    float* out = (float*)d_out;

    const int n_nodes = in_sizes[0] / NF;
    const int E  = in_sizes[1] / 2;
    const int ET = E + n_nodes;

    const int gemm_blocks  = (n_nodes + 15) / 16;
    const int edge_tblocks = (ET + 255) / 256;
    const int edge_wblocks = (ET + 7) / 8;

    k0_detect<<<1, 1024>>>((const int*)ei, E);
    k1_gemm1<<<gemm_blocks, 256>>>(x, W1, n_nodes);
    k1b_alpha1<<<n_nodes, 256>>>(as1, ad1);
    k2_den1<<<edge_tblocks, 256>>>(ei, E, ET);
    k3_agg1<<<edge_wblocks, 256>>>(ei, E, ET);
    k4_gemm2<<<gemm_blocks, 128>>>(W2, b1, n_nodes);
    k4b_alpha2<<<n_nodes, 128>>>(as2, ad2, b2, out);
    k5_den2<<<edge_tblocks, 256>>>(ei, E, ET);
    k6_agg2<<<edge_wblocks, 256>>>(ei, E, ET, out);
}

// round 3
// speedup vs baseline: 1.9146x; 1.9146x over previous
#include <cuda_runtime.h>
#include <cuda_bf16.h>

#define NMAX   50016
#define EMAX   800000
#define NF     128
#define HH     256
#define OUT2   128
#define NHEADS 4
#define NEG    0.2f

// ---- scratch ----
__device__ float g_h1  [(size_t)NMAX * HH];
__device__ float g_agg1[(size_t)NMAX * HH];
__device__ float g_h2  [(size_t)NMAX * OUT2];
__device__ float g_as1[NMAX * NHEADS];
__device__ float g_ad1[NMAX * NHEADS];
__device__ float g_as2[NMAX];
__device__ float g_ad2[NMAX];
__device__ int   g_is64;
// CSR
__device__ int   g_cnt [NMAX + 1];
__device__ int   g_off [NMAX + 1];
__device__ int   g_cur [NMAX + 1];
__device__ int   g_bsum[64];
__device__ int   g_boff[64];
__device__ int   g_csrc[EMAX];
__device__ int   g_cdst[EMAX];
__device__ float g_w1  [(size_t)EMAX * NHEADS];
__device__ float g_w2  [EMAX];

__device__ __forceinline__ float warp_sum(float v) {
    #pragma unroll
    for (int o = 16; o > 0; o >>= 1) v += __shfl_xor_sync(0xffffffffu, v, o);
    return v;
}

__device__ __forceinline__ void load_edge(const void* ei, int E, int i,
                                          int& s, int& d) {
    if (g_is64) {
        const long long* p = (const long long*)ei;
        s = (int)p[i]; d = (int)p[(size_t)E + i];
    } else {
        const int* p = (const int*)ei;
        s = p[i]; d = p[E + i];
    }
}

__device__ __forceinline__ float lrelu_exp(float v) {
    v = v > 0.f ? v : NEG * v;
    return __expf(v);
}

// ============ K0: edge dtype probe ============
__global__ void k0_detect(const int* ei32, int E) {
    __shared__ int flag;
    if (threadIdx.x == 0) flag = 0;
    __syncthreads();
    for (int j = threadIdx.x; j < 2048; j += blockDim.x) {
        int idx = 2 * j + 1;
        if (idx < 2 * E && ei32[idx] != 0) flag = 1;
    }
    __syncthreads();
    if (threadIdx.x == 0) g_is64 = (flag == 0);
}

// ============ CSR build ============
__global__ void kc1_zero(int n) {
    int i = blockIdx.x * blockDim.x + threadIdx.x;
    if (i <= n) g_cnt[i] = 0;
}
__global__ void kc2_count(const void* __restrict__ ei, int E) {
    int i = blockIdx.x * blockDim.x + threadIdx.x;
    if (i >= E) return;
    int s, d; load_edge(ei, E, i, s, d);
    atomicAdd(&g_cnt[d], 1);
}
__global__ void s1_scan(int n) {
    __shared__ int sd[1024];
    int tid = threadIdx.x;
    int i = blockIdx.x * 1024 + tid;
    int v = (i < n) ? g_cnt[i] : 0;
    sd[tid] = v;
    __syncthreads();
    #pragma unroll
    for (int off = 1; off < 1024; off <<= 1) {
        int t = (tid >= off) ? sd[tid - off] : 0;
        __syncthreads();
        sd[tid] += t;
        __syncthreads();
    }
    if (i < n) g_off[i] = sd[tid] - v;       // exclusive within block
    if (tid == 1023) g_bsum[blockIdx.x] = sd[1023];
}
__global__ void s2_scan(int nb) {
    if (threadIdx.x == 0) {
        int acc = 0;
        for (int b = 0; b < nb; b++) { int t = g_bsum[b]; g_boff[b] = acc; acc += t; }
    }
}
__global__ void s3_scan(int n, int E) {
    int i = blockIdx.x * 1024 + threadIdx.x;
    if (i < n) {
        int v = g_off[i] + g_boff[blockIdx.x];
        g_off[i] = v;
        g_cur[i] = v;
    }
    if (i == 0) g_off[n] = E;
}
__global__ void kc3_fill(const void* __restrict__ ei, int E) {
    int i = blockIdx.x * blockDim.x + threadIdx.x;
    if (i >= E) return;
    int s, d; load_edge(ei, E, i, s, d);
    int p = atomicAdd(&g_cur[d], 1);
    g_csrc[p] = s;
    g_cdst[p] = d;
}

// ============ K1: h1 = x @ W1  (Nx128 @ 128x256), float4 weights ============
__global__ void k1_gemm1(const float* __restrict__ x, const float* __restrict__ W1,
                         int n_nodes) {
    __shared__ float xs[16][NF];
    const int n0 = blockIdx.x * 16;
    const int tid = threadIdx.x;   // 256
    for (int i = tid; i < 16 * NF / 4; i += 256) {
        int nn = i >> 5, k4 = i & 31;
        int g = n0 + nn;
        float4 v = (g < n_nodes) ? *reinterpret_cast<const float4*>(x + (size_t)g * NF + 4 * k4)
                                 : make_float4(0.f, 0.f, 0.f, 0.f);
        *reinterpret_cast<float4*>(&xs[nn][4 * k4]) = v;
    }
    __syncthreads();
    const int tx = tid & 63, ty = tid >> 6;   // cols 4tx..4tx+3, node group ty
    float4 acc[4] = {};
    #pragma unroll 4
    for (int k = 0; k < NF; k++) {
        float4 w = *reinterpret_cast<const float4*>(W1 + (size_t)k * HH + 4 * tx);
        #pragma unroll
        for (int t = 0; t < 4; t++) {
            float a = xs[ty * 4 + t][k];
            acc[t].x += a * w.x; acc[t].y += a * w.y;
            acc[t].z += a * w.z; acc[t].w += a * w.w;
        }
    }
    #pragma unroll
    for (int t = 0; t < 4; t++) {
        int g = n0 + ty * 4 + t;
        if (g < n_nodes)
            *reinterpret_cast<float4*>(g_h1 + (size_t)g * HH + 4 * tx) = acc[t];
    }
}

// ============ K1b: per-node attention logits ============
__global__ void k1b_alpha1(const float* __restrict__ att_src,
                           const float* __restrict__ att_dst) {
    const int n = blockIdx.x;
    const int j = threadIdx.x;   // 256
    float v = g_h1[(size_t)n * HH + j];
    float sv = warp_sum(v * att_src[j]);
    float dv = warp_sum(v * att_dst[j]);
    __shared__ float rs[8], rd[8];
    int w = j >> 5, lane = j & 31;
    if (lane == 0) { rs[w] = sv; rd[w] = dv; }
    __syncthreads();
    if (j < NHEADS) {
        g_as1[n * NHEADS + j] = rs[2 * j] + rs[2 * j + 1];
        g_ad1[n * NHEADS + j] = rd[2 * j] + rd[2 * j + 1];
    }
}

// ============ KW1: per-edge softmax numerators (layer 1) ============
__global__ void kw1(int E) {
    int p = blockIdx.x * blockDim.x + threadIdx.x;
    if (p >= E) return;
    int s = g_csrc[p], d = g_cdst[p];
    float4 as = *reinterpret_cast<const float4*>(g_as1 + 4 * s);
    float4 ad = *reinterpret_cast<const float4*>(g_ad1 + 4 * d);
    float4 w;
    w.x = lrelu_exp(as.x + ad.x);
    w.y = lrelu_exp(as.y + ad.y);
    w.z = lrelu_exp(as.z + ad.z);
    w.w = lrelu_exp(as.w + ad.w);
    *reinterpret_cast<float4*>(g_w1 + (size_t)p * 4) = w;
}

// ============ KA1: gather aggregation, layer 1 (block per node) ============
__global__ void ka1(int n_nodes) {
    const int d = blockIdx.x;
    const int j = threadIdx.x;    // 256
    const int h = j >> 6;
    float ad = g_ad1[d * NHEADS + h];
    // self loop
    float w = lrelu_exp(g_as1[d * NHEADS + h] + ad);
    float den = w;
    float acc = w * g_h1[(size_t)d * HH + j];
    const int p1 = g_off[d + 1];
    #pragma unroll 4
    for (int p = g_off[d]; p < p1; p++) {
        int s = g_csrc[p];
        float wp = g_w1[(size_t)p * 4 + h];
        den += wp;
        acc += wp * g_h1[(size_t)s * HH + j];
    }
    g_agg1[(size_t)d * HH + j] = acc / den;
}

// ============ K4: h2 = elu(agg1 + b1) @ W2  (Nx256 @ 256x128) ============
__global__ void k4_gemm2(const float* __restrict__ W2, const float* __restrict__ b1,
                         int n_nodes) {
    __shared__ float xs[16][HH];   // 16 KB
    const int n0 = blockIdx.x * 16;
    const int tid = threadIdx.x;   // 128
    for (int i = tid; i < 16 * HH; i += 128) {
        int nn = i >> 8, k = i & 255;
        int g = n0 + nn;
        float v = 0.f;
        if (g < n_nodes) {
            v = g_agg1[(size_t)g * HH + k] + b1[k];
            v = v > 0.f ? v : expm1f(v);
        }
        xs[nn][k] = v;
    }
    __syncthreads();
    const int tx = tid & 31, ty = tid >> 5;   // cols 4tx..4tx+3
    float4 acc[4] = {};
    #pragma unroll 4
    for (int k = 0; k < HH; k++) {
        float4 w = *reinterpret_cast<const float4*>(W2 + (size_t)k * OUT2 + 4 * tx);
        #pragma unroll
        for (int t = 0; t < 4; t++) {
            float a = xs[ty * 4 + t][k];
            acc[t].x += a * w.x; acc[t].y += a * w.y;
            acc[t].z += a * w.z; acc[t].w += a * w.w;
        }
    }
    #pragma unroll
    for (int t = 0; t < 4; t++) {
        int g = n0 + ty * 4 + t;
        if (g < n_nodes)
            *reinterpret_cast<float4*>(g_h2 + (size_t)g * OUT2 + 4 * tx) = acc[t];
    }
}

// ============ K4b: layer-2 logits ============
__global__ void k4b_alpha2(const float* __restrict__ att_src,
                           const float* __restrict__ att_dst) {
    const int n = blockIdx.x;
    const int j = threadIdx.x;   // 128
    float v = g_h2[(size_t)n * OUT2 + j];
    float sv = warp_sum(v * att_src[j]);
    float dv = warp_sum(v * att_dst[j]);
    __shared__ float rs[4], rd[4];
    int w = j >> 5, lane = j & 31;
    if (lane == 0) { rs[w] = sv; rd[w] = dv; }
    __syncthreads();
    if (j == 0) {
        g_as2[n] = rs[0] + rs[1] + rs[2] + rs[3];
        g_ad2[n] = rd[0] + rd[1] + rd[2] + rd[3];
    }
}

// ============ KW2: per-edge softmax numerators (layer 2) ============
__global__ void kw2(int E) {
    int p = blockIdx.x * blockDim.x + threadIdx.x;
    if (p >= E) return;
    int s = g_csrc[p], d = g_cdst[p];
    g_w2[p] = lrelu_exp(g_as2[s] + g_ad2[d]);
}

// ============ KA2: gather aggregation, layer 2 ============
__global__ void ka2(int n_nodes, const float* __restrict__ b2,
                    float* __restrict__ out) {
    const int d = blockIdx.x;
    const int j = threadIdx.x;   // 128
    float ad = g_ad2[d];
    float w = lrelu_exp(g_as2[d] + ad);
    float den = w;
    float acc = w * g_h2[(size_t)d * OUT2 + j];
    const int p1 = g_off[d + 1];
    #pragma unroll 4
    for (int p = g_off[d]; p < p1; p++) {
        int s = g_csrc[p];
        float wp = g_w2[p];
        den += wp;
        acc += wp * g_h2[(size_t)s * OUT2 + j];
    }
    out[(size_t)d * OUT2 + j] = acc / den + b2[j];
}

extern "C" void kernel_launch(void* const* d_in, const int* in_sizes, int n_in,
                              void* d_out, int out_size) {
    const float* x    = (const float*)d_in[0];
    const void*  ei   = d_in[1];
    const float* W1   = (const float*)d_in[2];
    const float* as1  = (const float*)d_in[3];
    const float* ad1  = (const float*)d_in[4];
    const float* b1   = (const float*)d_in[5];
    const float* W2   = (const float*)d_in[6];
    const float* as2  = (const float*)d_in[7];
    const float* ad2  = (const float*)d_in[8];
    const float* b2   = (const float*)d_in[9];
    float* out = (float*)d_out;

    const int n_nodes = in_sizes[0] / NF;
    const int E  = in_sizes[1] / 2;

    const int gemm_blocks = (n_nodes + 15) / 16;
    const int eb  = (E + 255) / 256;
    const int nb  = (n_nodes + 1023) / 1024;

    k0_detect<<<1, 1024>>>((const int*)ei, E);
    kc1_zero<<<nb + 1, 1024>>>(n_nodes);
    kc2_count<<<eb, 256>>>(ei, E);
    s1_scan<<<nb, 1024>>>(n_nodes);
    s2_scan<<<1, 32>>>(nb);
    s3_scan<<<nb, 1024>>>(n_nodes, E);
    kc3_fill<<<eb, 256>>>(ei, E);

    k1_gemm1<<<gemm_blocks, 256>>>(x, W1, n_nodes);
    k1b_alpha1<<<n_nodes, 256>>>(as1, ad1);
    kw1<<<eb, 256>>>(E);
    ka1<<<n_nodes, 256>>>(n_nodes);

    k4_gemm2<<<gemm_blocks, 128>>>(W2, b1, n_nodes);
    k4b_alpha2<<<n_nodes, 128>>>(as2, ad2);
    kw2<<<eb, 256>>>(E);
    ka2<<<n_nodes, 128>>>(n_nodes, b2, out);
}

// round 4
// speedup vs baseline: 1.9489x; 1.0179x over previous
#include <cuda_runtime.h>
#include <cuda_bf16.h>

#define NMAX   50016
#define EMAX   800000
#define NF     128
#define HH     256
#define OUT2   128
#define NHEADS 4
#define NEG    0.2f

// ---- scratch ----
__device__ float g_h1  [(size_t)NMAX * HH];
__device__ float g_agg1[(size_t)NMAX * HH];
__device__ float g_h2  [(size_t)NMAX * OUT2];
__device__ float g_as1[NMAX * NHEADS];
__device__ float g_ad1[NMAX * NHEADS];
__device__ float g_as2[NMAX];
__device__ float g_ad2[NMAX];
__device__ float g_va1[NF * 8];      // W1 @ [att_src1 | att_dst1] per head
__device__ float g_wa2[HH * 2];      // W2 @ [att_src2 | att_dst2]
__device__ int   g_is64;
// CSR
__device__ int   g_cnt [NMAX + 1];
__device__ int   g_off [NMAX + 1];
__device__ int   g_cur [NMAX + 1];
__device__ int   g_bsum[64];
__device__ int   g_boff[64];
__device__ int   g_csrc[EMAX];
__device__ int   g_cdst[EMAX];
__device__ float g_w1  [(size_t)EMAX * NHEADS];
__device__ float g_w2  [EMAX];

__device__ __forceinline__ void load_edge(const void* ei, int E, int i,
                                          int& s, int& d) {
    if (g_is64) {
        const long long* p = (const long long*)ei;
        s = (int)p[i]; d = (int)p[(size_t)E + i];
    } else {
        const int* p = (const int*)ei;
        s = p[i]; d = p[E + i];
    }
}

__device__ __forceinline__ float lrelu_exp(float v) {
    v = v > 0.f ? v : NEG * v;
    return __expf(v);
}

#define FMA2(acc, a2, w2) \
    asm("fma.rn.f32x2 %0, %1, %2, %0;" : "+l"(acc) : "l"(a2), "l"(w2))
#define PACK2(a2, f) \
    asm("mov.b64 %0, {%1, %1};" : "=l"(a2) : "r"(__float_as_uint(f)))

// ============ K0: edge dtype probe ============
__global__ void k0_detect(const int* ei32, int E) {
    __shared__ int flag;
    if (threadIdx.x == 0) flag = 0;
    __syncthreads();
    for (int j = threadIdx.x; j < 2048; j += blockDim.x) {
        int idx = 2 * j + 1;
        if (idx < 2 * E && ei32[idx] != 0) flag = 1;
    }
    __syncthreads();
    if (threadIdx.x == 0) g_is64 = (flag == 0);
}

// ============ CSR build ============
__global__ void kc1_zero(int n) {
    int i = blockIdx.x * blockDim.x + threadIdx.x;
    if (i <= n) g_cnt[i] = 0;
}
__global__ void kc2_count(const void* __restrict__ ei, int E) {
    int i = blockIdx.x * blockDim.x + threadIdx.x;
    if (i >= E) return;
    int s, d; load_edge(ei, E, i, s, d);
    atomicAdd(&g_cnt[d], 1);
}
__global__ void s1_scan(int n) {
    __shared__ int sd[1024];
    int tid = threadIdx.x;
    int i = blockIdx.x * 1024 + tid;
    int v = (i < n) ? g_cnt[i] : 0;
    sd[tid] = v;
    __syncthreads();
    #pragma unroll
    for (int off = 1; off < 1024; off <<= 1) {
        int t = (tid >= off) ? sd[tid - off] : 0;
        __syncthreads();
        sd[tid] += t;
        __syncthreads();
    }
    if (i < n) g_off[i] = sd[tid] - v;
    if (tid == 1023) g_bsum[blockIdx.x] = sd[1023];
}
__global__ void s2_scan(int nb) {
    if (threadIdx.x == 0) {
        int acc = 0;
        for (int b = 0; b < nb; b++) { int t = g_bsum[b]; g_boff[b] = acc; acc += t; }
    }
}
__global__ void s3_scan(int n, int E) {
    int i = blockIdx.x * 1024 + threadIdx.x;
    if (i < n) {
        int v = g_off[i] + g_boff[blockIdx.x];
        g_off[i] = v;
        g_cur[i] = v;
    }
    if (i == 0) g_off[n] = E;
}
__global__ void kc3_fill(const void* __restrict__ ei, int E) {
    int i = blockIdx.x * blockDim.x + threadIdx.x;
    if (i >= E) return;
    int s, d; load_edge(ei, E, i, s, d);
    int p = atomicAdd(&g_cur[d], 1);
    g_csrc[p] = s;
    g_cdst[p] = d;
}

// ============ KV1: va1 = W1 @ [a_src1|a_dst1] (per head) ============
__global__ void kv1(const float* __restrict__ W1, const float* __restrict__ as,
                    const float* __restrict__ ad) {
    for (int q = threadIdx.x; q < NF * 8; q += 256) {
        int k = q >> 3, o = q & 7, h = o & 3;
        const float* a = (o < 4 ? as : ad) + h * 64;
        const float* w = W1 + (size_t)k * HH + h * 64;
        float s = 0.f;
        #pragma unroll 8
        for (int c = 0; c < 64; c++) s += w[c] * a[c];
        g_va1[q] = s;
    }
}

// ============ KV2: wa2 = W2 @ [a_src2|a_dst2] ============
__global__ void kv2(const float* __restrict__ W2, const float* __restrict__ as,
                    const float* __restrict__ ad) {
    for (int q = threadIdx.x; q < HH * 2; q += 256) {
        int k = q >> 1, o = q & 1;
        const float* a = o ? ad : as;
        const float* w = W2 + (size_t)k * OUT2;
        float s = 0.f;
        #pragma unroll 8
        for (int c = 0; c < OUT2; c++) s += w[c] * a[c];
        g_wa2[q] = s;
    }
}

// ============ K1: h1 = x @ W1  (f32x2 packed FFMA) ============
__global__ void k1_gemm1(const float* __restrict__ x, const float* __restrict__ W1,
                         int n_nodes) {
    __shared__ float xs[NF][17];      // transposed A tile, 16 nodes
    const int n0 = blockIdx.x * 16;
    const int tid = threadIdx.x;      // 256
    {
        int i = tid;
        #pragma unroll
        for (int r = 0; r < 2; r++, i += 256) {
            int nn = i >> 5, k4 = i & 31;
            int g = n0 + nn;
            float4 v = make_float4(0.f, 0.f, 0.f, 0.f);
            if (g < n_nodes) v = *reinterpret_cast<const float4*>(x + (size_t)g * NF + 4 * k4);
            xs[4 * k4 + 0][nn] = v.x; xs[4 * k4 + 1][nn] = v.y;
            xs[4 * k4 + 2][nn] = v.z; xs[4 * k4 + 3][nn] = v.w;
        }
    }
    __syncthreads();
    const int tx = tid & 63, ty = tid >> 6;    // cols 4tx..4tx+3, nodes 4ty..4ty+3
    unsigned long long acc[4][2] = {};
    const float* wp = W1 + 4 * tx;
    #pragma unroll 8
    for (int k = 0; k < NF; k++) {
        ulonglong2 w = *reinterpret_cast<const ulonglong2*>(wp + (size_t)k * HH);
        #pragma unroll
        for (int t = 0; t < 4; t++) {
            unsigned long long a2;
            PACK2(a2, xs[k][ty * 4 + t]);
            FMA2(acc[t][0], a2, w.x);
            FMA2(acc[t][1], a2, w.y);
        }
    }
    #pragma unroll
    for (int t = 0; t < 4; t++) {
        int g = n0 + ty * 4 + t;
        if (g < n_nodes) {
            float4 o;
            o.x = __uint_as_float((unsigned)(acc[t][0]));
            o.y = __uint_as_float((unsigned)(acc[t][0] >> 32));
            o.z = __uint_as_float((unsigned)(acc[t][1]));
            o.w = __uint_as_float((unsigned)(acc[t][1] >> 32));
            *reinterpret_cast<float4*>(g_h1 + (size_t)g * HH + 4 * tx) = o;
        }
    }
}

// ============ KS1: layer-1 logits  as1/ad1 = x @ va1 ============
__global__ void ks_alpha1(const float* __restrict__ x, int n_nodes) {
    __shared__ float xv[32][NF];      // 16 KB
    __shared__ float sva[NF * 8];     // 4 KB
    const int n0 = blockIdx.x * 32;
    const int tid = threadIdx.x;      // 256
    for (int i = tid; i < NF * 8; i += 256) sva[i] = g_va1[i];
    #pragma unroll
    for (int r = 0; r < 4; r++) {
        int i = tid + r * 256;
        int nn = i >> 5, k4 = i & 31;
        int g = n0 + nn;
        float4 v = make_float4(0.f, 0.f, 0.f, 0.f);
        if (g < n_nodes) v = *reinterpret_cast<const float4*>(x + (size_t)g * NF + 4 * k4);
        *reinterpret_cast<float4*>(&xv[nn][4 * k4]) = v;
    }
    __syncthreads();
    int nn = tid >> 3, o = tid & 7;
    int g = n0 + nn;
    float s = 0.f;
    #pragma unroll 8
    for (int k = 0; k < NF; k++) s += xv[nn][k] * sva[k * 8 + o];
    if (g < n_nodes) {
        if (o < 4) g_as1[g * 4 + o] = s;
        else       g_ad1[g * 4 + o - 4] = s;
    }
}

// ============ KW1: per-edge softmax numerators (layer 1) ============
__global__ void kw1(int E) {
    int p = blockIdx.x * blockDim.x + threadIdx.x;
    if (p >= E) return;
    int s = g_csrc[p], d = g_cdst[p];
    float4 as = *reinterpret_cast<const float4*>(g_as1 + 4 * s);
    float4 ad = *reinterpret_cast<const float4*>(g_ad1 + 4 * d);
    float4 w;
    w.x = lrelu_exp(as.x + ad.x);
    w.y = lrelu_exp(as.y + ad.y);
    w.z = lrelu_exp(as.z + ad.z);
    w.w = lrelu_exp(as.w + ad.w);
    *reinterpret_cast<float4*>(g_w1 + (size_t)p * 4) = w;
}

// ============ KA1: gather aggregation, layer 1 ============
__global__ void ka1(int n_nodes) {
    const int d = blockIdx.x;
    const int j = threadIdx.x;    // 256
    const int h = j >> 6;
    float ad = g_ad1[d * NHEADS + h];
    float w = lrelu_exp(g_as1[d * NHEADS + h] + ad);
    float den = w;
    float acc = w * g_h1[(size_t)d * HH + j];
    const int p1 = g_off[d + 1];
    #pragma unroll 4
    for (int p = g_off[d]; p < p1; p++) {
        int s = g_csrc[p];
        float wp = g_w1[(size_t)p * 4 + h];
        den += wp;
        acc += wp * g_h1[(size_t)s * HH + j];
    }
    g_agg1[(size_t)d * HH + j] = acc / den;
}

// ============ K4: h2 = elu(agg1+b1) @ W2 (f32x2) + layer-2 logits ============
__global__ void k4_gemm2(const float* __restrict__ W2, const float* __restrict__ b1,
                         int n_nodes) {
    __shared__ float xs[HH][17];      // transposed elu'd tile, 16 nodes (~17.4 KB)
    __shared__ float swa[HH * 2];     // 2 KB
    const int n0 = blockIdx.x * 16;
    const int tid = threadIdx.x;      // 128
    for (int i = tid; i < HH * 2; i += 128) swa[i] = g_wa2[i];
    #pragma unroll
    for (int r = 0; r < 8; r++) {
        int i = tid + r * 128;        // 1024 float4 tasks
        int nn = i >> 6, k4 = i & 63;
        int g = n0 + nn;
        float4 v = make_float4(0.f, 0.f, 0.f, 0.f);
        if (g < n_nodes) {
            v = *reinterpret_cast<const float4*>(g_agg1 + (size_t)g * HH + 4 * k4);
            v.x += b1[4 * k4 + 0]; v.y += b1[4 * k4 + 1];
            v.z += b1[4 * k4 + 2]; v.w += b1[4 * k4 + 3];
            v.x = v.x > 0.f ? v.x : expm1f(v.x);
            v.y = v.y > 0.f ? v.y : expm1f(v.y);
            v.z = v.z > 0.f ? v.z : expm1f(v.z);
            v.w = v.w > 0.f ? v.w : expm1f(v.w);
        }
        xs[4 * k4 + 0][nn] = v.x; xs[4 * k4 + 1][nn] = v.y;
        xs[4 * k4 + 2][nn] = v.z; xs[4 * k4 + 3][nn] = v.w;
    }
    __syncthreads();
    const int tx = tid & 31, ty = tid >> 5;
    unsigned long long acc[4][2] = {};
    const float* wp = W2 + 4 * tx;
    #pragma unroll 8
    for (int k = 0; k < HH; k++) {
        ulonglong2 w = *reinterpret_cast<const ulonglong2*>(wp + (size_t)k * OUT2);
        #pragma unroll
        for (int t = 0; t < 4; t++) {
            unsigned long long a2;
            PACK2(a2, xs[k][ty * 4 + t]);
            FMA2(acc[t][0], a2, w.x);
            FMA2(acc[t][1], a2, w.y);
        }
    }
    #pragma unroll
    for (int t = 0; t < 4; t++) {
        int g = n0 + ty * 4 + t;
        if (g < n_nodes) {
            float4 o;
            o.x = __uint_as_float((unsigned)(acc[t][0]));
            o.y = __uint_as_float((unsigned)(acc[t][0] >> 32));
            o.z = __uint_as_float((unsigned)(acc[t][1]));
            o.w = __uint_as_float((unsigned)(acc[t][1] >> 32));
            *reinterpret_cast<float4*>(g_h2 + (size_t)g * OUT2 + 4 * tx) = o;
        }
    }
    // layer-2 logits from the elu'd input rows already in smem
    if (tid < 32) {
        int nn = tid >> 1, o = tid & 1;
        float s = 0.f;
        #pragma unroll 8
        for (int k = 0; k < HH; k++) s += xs[k][nn] * swa[2 * k + o];
        int g = n0 + nn;
        if (g < n_nodes) {
            if (o == 0) g_as2[g] = s;
            else        g_ad2[g] = s;
        }
    }
}

// ============ KW2: per-edge softmax numerators (layer 2) ============
__global__ void kw2(int E) {
    int p = blockIdx.x * blockDim.x + threadIdx.x;
    if (p >= E) return;
    int s = g_csrc[p], d = g_cdst[p];
    g_w2[p] = lrelu_exp(g_as2[s] + g_ad2[d]);
}

// ============ KA2: gather aggregation, layer 2 ============
__global__ void ka2(int n_nodes, const float* __restrict__ b2,
                    float* __restrict__ out) {
    const int d = blockIdx.x;
    const int j = threadIdx.x;   // 128
    float ad = g_ad2[d];
    float w = lrelu_exp(g_as2[d] + ad);
    float den = w;
    float acc = w * g_h2[(size_t)d * OUT2 + j];
    const int p1 = g_off[d + 1];
    #pragma unroll 4
    for (int p = g_off[d]; p < p1; p++) {
        int s = g_csrc[p];
        float wp = g_w2[p];
        den += wp;
        acc += wp * g_h2[(size_t)s * OUT2 + j];
    }
    out[(size_t)d * OUT2 + j] = acc / den + b2[j];
}

extern "C" void kernel_launch(void* const* d_in, const int* in_sizes, int n_in,
                              void* d_out, int out_size) {
    const float* x    = (const float*)d_in[0];
    const void*  ei   = d_in[1];
    const float* W1   = (const float*)d_in[2];
    const float* as1  = (const float*)d_in[3];
    const float* ad1  = (const float*)d_in[4];
    const float* b1   = (const float*)d_in[5];
    const float* W2   = (const float*)d_in[6];
    const float* as2  = (const float*)d_in[7];
    const float* ad2  = (const float*)d_in[8];
    const float* b2   = (const float*)d_in[9];
    float* out = (float*)d_out;

    const int n_nodes = in_sizes[0] / NF;
    const int E  = in_sizes[1] / 2;

    const int gemm_blocks = (n_nodes + 15) / 16;
    const int eb = (E + 255) / 256;
    const int nb = (n_nodes + 1023) / 1024;

    k0_detect<<<1, 1024>>>((const int*)ei, E);
    kc1_zero<<<nb + 1, 1024>>>(n_nodes);
    kc2_count<<<eb, 256>>>(ei, E);
    s1_scan<<<nb, 1024>>>(n_nodes);
    s2_scan<<<1, 32>>>(nb);
    s3_scan<<<nb, 1024>>>(n_nodes, E);
    kc3_fill<<<eb, 256>>>(ei, E);

    kv1<<<1, 256>>>(W1, as1, ad1);
    kv2<<<1, 256>>>(W2, as2, ad2);
    k1_gemm1<<<gemm_blocks, 256>>>(x, W1, n_nodes);
    ks_alpha1<<<(n_nodes + 31) / 32, 256>>>(x, n_nodes);
    kw1<<<eb, 256>>>(E);
    ka1<<<n_nodes, 256>>>(n_nodes);

    k4_gemm2<<<gemm_blocks, 128>>>(W2, b1, n_nodes);
    kw2<<<eb, 256>>>(E);
    ka2<<<n_nodes, 128>>>(n_nodes, b2, out);
}

// round 6
// speedup vs baseline: 2.2627x; 1.1610x over previous
#include <cuda_runtime.h>
#include <cuda_bf16.h>

#define NMAX   50016
#define EMAX   800000
#define NF     128
#define HH     256
#define OUT2   128
#define NHEADS 4
#define NEG    0.2f

// ---- scratch ----
__device__ float g_h1  [(size_t)NMAX * HH];
__device__ float g_agg1[(size_t)NMAX * HH];
__device__ float g_h2  [(size_t)NMAX * OUT2];
__device__ float g_as1[NMAX * NHEADS];
__device__ float g_ad1[NMAX * NHEADS];
__device__ float g_as2[NMAX];
__device__ float g_ad2[NMAX];
__device__ float g_va1[NF * 8];      // W1 @ [att_src1 | att_dst1] per head
__device__ float g_wa2[HH * 2];      // W2 @ [att_src2 | att_dst2]
__device__ int   g_is64;
// CSR
__device__ int   g_cnt [NMAX + 1];
__device__ int   g_off [NMAX + 1];
__device__ int   g_cur [NMAX + 1];
__device__ int   g_bsum[64];
__device__ int   g_boff[64];
__device__ int   g_csrc[EMAX];
__device__ float g_w1  [(size_t)EMAX * NHEADS];

__device__ __forceinline__ void load_edge(const void* ei, int E, int i,
                                          int& s, int& d) {
    if (g_is64) {
        const long long* p = (const long long*)ei;
        s = (int)p[i]; d = (int)p[(size_t)E + i];
    } else {
        const int* p = (const int*)ei;
        s = p[i]; d = p[E + i];
    }
}

__device__ __forceinline__ float lrelu_exp(float v) {
    v = v > 0.f ? v : NEG * v;
    return __expf(v);
}

#define FMA2(acc, a2, w2) \
    asm("fma.rn.f32x2 %0, %1, %2, %0;" : "+l"(acc) : "l"(a2), "l"(w2))
#define PACK2(a2, f) \
    asm("mov.b64 %0, {%1, %1};" : "=l"(a2) : "r"(__float_as_uint(f)))

// ============ KZ: dtype probe + zero counts (fused) ============
__global__ void kz(const int* ei32, int E, int n) {
    int i = blockIdx.x * 1024 + threadIdx.x;
    if (i <= n) g_cnt[i] = 0;
    if (blockIdx.x == 0) {
        __shared__ int flag;
        if (threadIdx.x == 0) flag = 0;
        __syncthreads();
        for (int j = threadIdx.x; j < 2048; j += 1024) {
            int idx = 2 * j + 1;
            if (idx < 2 * E && ei32[idx] != 0) flag = 1;
        }
        __syncthreads();
        if (threadIdx.x == 0) g_is64 = (flag == 0);
    }
}

// ============ KC2: count in-degrees ============
__global__ void kc2_count(const void* __restrict__ ei, int E) {
    int i = blockIdx.x * blockDim.x + threadIdx.x;
    if (i >= E) return;
    int s, d; load_edge(ei, E, i, s, d);
    atomicAdd(&g_cnt[d], 1);
}

// ============ KV: small attention-vector precomputes (fused) ============
__global__ void kv(const float* __restrict__ W1, const float* __restrict__ a_s1,
                   const float* __restrict__ a_d1, const float* __restrict__ W2,
                   const float* __restrict__ a_s2, const float* __restrict__ a_d2) {
    int t = blockIdx.x * 256 + threadIdx.x;
    if (t < NF * 8) {
        int k = t >> 3, o = t & 7, h = o & 3;
        const float* a = (o < 4 ? a_s1 : a_d1) + h * 64;
        const float* w = W1 + (size_t)k * HH + h * 64;
        float s = 0.f;
        #pragma unroll 8
        for (int c = 0; c < 64; c++) s += w[c] * a[c];
        g_va1[t] = s;
    } else if (t < NF * 8 + HH * 2) {
        int q = t - NF * 8;
        int k = q >> 1, o = q & 1;
        const float* a = o ? a_d2 : a_s2;
        const float* w = W2 + (size_t)k * OUT2;
        float s = 0.f;
        #pragma unroll 8
        for (int c = 0; c < OUT2; c++) s += w[c] * a[c];
        g_wa2[q] = s;
    }
}

// ============ K1: h1 = x @ W1 (32-row tile, f32x2) + layer-1 logits ============
__global__ void k1_gemm1(const float* __restrict__ x, const float* __restrict__ W1,
                         int n_nodes) {
    __shared__ float xs[32][NF + 4];    // stride 132: float4-aligned + bank-rotated
    __shared__ float sva[NF * 8];       // 4 KB
    const int n0 = blockIdx.x * 32;
    const int tid = threadIdx.x;        // 256
    for (int i = tid; i < NF * 8; i += 256) sva[i] = g_va1[i];
    #pragma unroll
    for (int r = 0; r < 4; r++) {
        int i = tid + r * 256;
        int nn = i >> 5, k4 = i & 31;
        int g = n0 + nn;
        float4 v = make_float4(0.f, 0.f, 0.f, 0.f);
        if (g < n_nodes) v = *reinterpret_cast<const float4*>(x + (size_t)g * NF + 4 * k4);
        *reinterpret_cast<float4*>(&xs[nn][4 * k4]) = v;
    }
    __syncthreads();
    const int tx = tid & 63, ty = tid >> 6;    // cols 4tx..4tx+3, nodes ty*8+t
    unsigned long long acc[8][2] = {};
    const float* wp = W1 + 4 * tx;
    #pragma unroll 4
    for (int k = 0; k < NF; k++) {
        ulonglong2 w = *reinterpret_cast<const ulonglong2*>(wp + (size_t)k * HH);
        #pragma unroll
        for (int t = 0; t < 8; t++) {
            unsigned long long a2;
            PACK2(a2, xs[ty * 8 + t][k]);
            FMA2(acc[t][0], a2, w.x);
            FMA2(acc[t][1], a2, w.y);
        }
    }
    #pragma unroll
    for (int t = 0; t < 8; t++) {
        int g = n0 + ty * 8 + t;
        if (g < n_nodes) {
            float4 o;
            o.x = __uint_as_float((unsigned)(acc[t][0]));
            o.y = __uint_as_float((unsigned)(acc[t][0] >> 32));
            o.z = __uint_as_float((unsigned)(acc[t][1]));
            o.w = __uint_as_float((unsigned)(acc[t][1] >> 32));
            *reinterpret_cast<float4*>(g_h1 + (size_t)g * HH + 4 * tx) = o;
        }
    }
    // fused layer-1 logits: 256 threads = 32 nodes x 8 outputs
    {
        int nn = tid >> 3, o = tid & 7;
        int g = n0 + nn;
        float s = 0.f;
        #pragma unroll 8
        for (int k = 0; k < NF; k++) s += xs[nn][k] * sva[k * 8 + o];
        if (g < n_nodes) {
            if (o < 4) g_as1[g * 4 + o] = s;
            else       g_ad1[g * 4 + o - 4] = s;
        }
    }
}

// ============ scan (3 small kernels) ============
__global__ void s1_scan(int n) {
    __shared__ int sd[1024];
    int tid = threadIdx.x;
    int i = blockIdx.x * 1024 + tid;
    int v = (i < n) ? g_cnt[i] : 0;
    sd[tid] = v;
    __syncthreads();
    #pragma unroll
    for (int off = 1; off < 1024; off <<= 1) {
        int t = (tid >= off) ? sd[tid - off] : 0;
        __syncthreads();
        sd[tid] += t;
        __syncthreads();
    }
    if (i < n) g_off[i] = sd[tid] - v;
    if (tid == 1023) g_bsum[blockIdx.x] = sd[1023];
}
__global__ void s2_scan(int nb) {
    if (threadIdx.x == 0) {
        int acc = 0;
        for (int b = 0; b < nb; b++) { int t = g_bsum[b]; g_boff[b] = acc; acc += t; }
    }
}
__global__ void s3_scan(int n, int E) {
    int i = blockIdx.x * 1024 + threadIdx.x;
    if (i < n) {
        int v = g_off[i] + g_boff[blockIdx.x];
        g_off[i] = v;
        g_cur[i] = v;
    }
    if (i == 0) g_off[n] = E;
}

// ============ KC3W1: CSR fill + layer-1 softmax numerators (fused) ============
__global__ void kc3w1(const void* __restrict__ ei, int E) {
    int i = blockIdx.x * blockDim.x + threadIdx.x;
    if (i >= E) return;
    int s, d; load_edge(ei, E, i, s, d);
    int p = atomicAdd(&g_cur[d], 1);
    g_csrc[p] = s;
    float4 as = *reinterpret_cast<const float4*>(g_as1 + 4 * s);
    float4 ad = *reinterpret_cast<const float4*>(g_ad1 + 4 * d);
    float4 w;
    w.x = lrelu_exp(as.x + ad.x);
    w.y = lrelu_exp(as.y + ad.y);
    w.z = lrelu_exp(as.z + ad.z);
    w.w = lrelu_exp(as.w + ad.w);
    *reinterpret_cast<float4*>(g_w1 + (size_t)p * 4) = w;
}

// ============ KA1: gather aggregation, layer 1 ============
__global__ void ka1(int n_nodes) {
    const int d = blockIdx.x;
    const int j = threadIdx.x;    // 256
    const int h = j >> 6;
    float ad = g_ad1[d * NHEADS + h];
    float w = lrelu_exp(g_as1[d * NHEADS + h] + ad);
    float den = w;
    float acc = w * g_h1[(size_t)d * HH + j];
    const int p1 = g_off[d + 1];
    #pragma unroll 4
    for (int p = g_off[d]; p < p1; p++) {
        int s = g_csrc[p];
        float wp = g_w1[(size_t)p * 4 + h];
        den += wp;
        acc += wp * g_h1[(size_t)s * HH + j];
    }
    g_agg1[(size_t)d * HH + j] = acc / den;
}

// ============ K4: h2 = elu(agg1+b1) @ W2 (32-row tile, f32x2) + logits ============
__global__ void k4_gemm2(const float* __restrict__ W2, const float* __restrict__ b1,
                         int n_nodes) {
    __shared__ float xs[32][HH + 4];    // stride 260: float4-aligned + bank-rotated
    __shared__ float swa[HH * 2];       // 2 KB
    const int n0 = blockIdx.x * 32;
    const int tid = threadIdx.x;        // 256
    for (int i = tid; i < HH * 2; i += 256) swa[i] = g_wa2[i];
    #pragma unroll
    for (int r = 0; r < 8; r++) {
        int i = tid + r * 256;          // 2048 float4 tasks
        int nn = i >> 6, k4 = i & 63;
        int g = n0 + nn;
        float4 v = make_float4(0.f, 0.f, 0.f, 0.f);
        if (g < n_nodes) {
            v = *reinterpret_cast<const float4*>(g_agg1 + (size_t)g * HH + 4 * k4);
            float4 b = *reinterpret_cast<const float4*>(b1 + 4 * k4);
            v.x += b.x; v.y += b.y; v.z += b.z; v.w += b.w;
            v.x = v.x > 0.f ? v.x : expm1f(v.x);
            v.y = v.y > 0.f ? v.y : expm1f(v.y);
            v.z = v.z > 0.f ? v.z : expm1f(v.z);
            v.w = v.w > 0.f ? v.w : expm1f(v.w);
        }
        *reinterpret_cast<float4*>(&xs[nn][4 * k4]) = v;
    }
    __syncthreads();
    const int tx = tid & 31, ty = tid >> 5;   // cols 4tx..4tx+3, nodes ty*4+t
    unsigned long long acc[4][2] = {};
    const float* wp = W2 + 4 * tx;
    #pragma unroll 4
    for (int k = 0; k < HH; k++) {
        ulonglong2 w = *reinterpret_cast<const ulonglong2*>(wp + (size_t)k * OUT2);
        #pragma unroll
        for (int t = 0; t < 4; t++) {
            unsigned long long a2;
            PACK2(a2, xs[ty * 4 + t][k]);
            FMA2(acc[t][0], a2, w.x);
            FMA2(acc[t][1], a2, w.y);
        }
    }
    #pragma unroll
    for (int t = 0; t < 4; t++) {
        int g = n0 + ty * 4 + t;
        if (g < n_nodes) {
            float4 o;
            o.x = __uint_as_float((unsigned)(acc[t][0]));
            o.y = __uint_as_float((unsigned)(acc[t][0] >> 32));
            o.z = __uint_as_float((unsigned)(acc[t][1]));
            o.w = __uint_as_float((unsigned)(acc[t][1] >> 32));
            *reinterpret_cast<float4*>(g_h2 + (size_t)g * OUT2 + 4 * tx) = o;
        }
    }
    // fused layer-2 logits: 64 threads = 32 nodes x 2 outputs
    if (tid < 64) {
        int nn = tid >> 1, o = tid & 1;
        float s = 0.f;
        #pragma unroll 8
        for (int k = 0; k < HH; k++) s += xs[nn][k] * swa[2 * k + o];
        int g = n0 + nn;
        if (g < n_nodes) {
            if (o == 0) g_as2[g] = s;
            else        g_ad2[g] = s;
        }
    }
}

// ============ KA2: gather aggregation, layer 2 (fused softmax weights) ============
__global__ void ka2(int n_nodes, const float* __restrict__ b2,
                    float* __restrict__ out) {
    __shared__ int   ssrc[128];
    __shared__ float sw[128];
    const int d = blockIdx.x;
    const int j = threadIdx.x;   // 128
    float add = g_ad2[d];
    float w0 = lrelu_exp(g_as2[d] + add);
    float den = w0;
    float acc = w0 * g_h2[(size_t)d * OUT2 + j];
    const int pB = g_off[d], pE = g_off[d + 1];
    for (int p0 = pB; p0 < pE; p0 += 128) {
        int np = min(128, pE - p0);
        __syncthreads();
        if (j < np) {
            int s = g_csrc[p0 + j];
            ssrc[j] = s;
            sw[j] = lrelu_exp(g_as2[s] + add);
        }
        __syncthreads();
        #pragma unroll 4
        for (int e = 0; e < np; e++) {
            int s = ssrc[e];
            float wp = sw[e];
            den += wp;
            acc += wp * g_h2[(size_t)s * OUT2 + j];
        }
    }
    out[(size_t)d * OUT2 + j] = acc / den + b2[j];
}

extern "C" void kernel_launch(void* const* d_in, const int* in_sizes, int n_in,
                              void* d_out, int out_size) {
    const float* x    = (const float*)d_in[0];
    const void*  ei   = d_in[1];
    const float* W1   = (const float*)d_in[2];
    const float* as1  = (const float*)d_in[3];
    const float* ad1  = (const float*)d_in[4];
    const float* b1   = (const float*)d_in[5];
    const float* W2   = (const float*)d_in[6];
    const float* as2  = (const float*)d_in[7];
    const float* ad2  = (const float*)d_in[8];
    const float* b2   = (const float*)d_in[9];
    float* out = (float*)d_out;

    const int n_nodes = in_sizes[0] / NF;
    const int E  = in_sizes[1] / 2;

    const int gemm_blocks = (n_nodes + 31) / 32;
    const int eb = (E + 255) / 256;
    const int nb = (n_nodes + 1023) / 1024;

    kz<<<nb + 1, 1024>>>((const int*)ei, E, n_nodes);          // 1
    kc2_count<<<eb, 256>>>(ei, E);                             // 2
    kv<<<6, 256>>>(W1, as1, ad1, W2, as2, ad2);                // 3
    k1_gemm1<<<gemm_blocks, 256>>>(x, W1, n_nodes);            // 4  <- profiled slot
    s1_scan<<<nb, 1024>>>(n_nodes);                            // 5
    s2_scan<<<1, 32>>>(nb);                                    // 6
    s3_scan<<<nb, 1024>>>(n_nodes, E);                         // 7
    kc3w1<<<eb, 256>>>(ei, E);                                 // 8
    ka1<<<n_nodes, 256>>>(n_nodes);                            // 9
    k4_gemm2<<<gemm_blocks, 256>>>(W2, b1, n_nodes);           // 10
    ka2<<<n_nodes, 128>>>(n_nodes, b2, out);                   // 11
}

// round 7
// speedup vs baseline: 2.2722x; 1.0042x over previous
#include <cuda_runtime.h>
#include <cuda_bf16.h>

#define NMAX   50016
#define EMAX   800000
#define NF     128
#define HH     256
#define OUT2   128
#define NHEADS 4
#define NEG    0.2f

// ---- scratch ----
__device__ float g_h1  [(size_t)NMAX * HH];
__device__ float g_agg1[(size_t)NMAX * HH];
__device__ float g_h2  [(size_t)NMAX * OUT2];
__device__ float g_as1[NMAX * NHEADS];
__device__ float g_ad1[NMAX * NHEADS];
__device__ float g_as2[NMAX];
__device__ float g_ad2[NMAX];
__device__ float g_va1[NF * 8];
__device__ float g_wa2[HH * 2];
__device__ int   g_is64;
// CSR
__device__ int   g_cnt [NMAX + 1];
__device__ int   g_off [NMAX + 1];
__device__ int   g_cur [NMAX + 1];
__device__ int   g_bsum[64];
__device__ int   g_boff[64];
__device__ int   g_csrc[EMAX];
__device__ float g_w1  [(size_t)EMAX * NHEADS];

__device__ __forceinline__ void load_edge(const void* ei, int E, int i,
                                          int& s, int& d) {
    if (g_is64) {
        const long long* p = (const long long*)ei;
        s = (int)p[i]; d = (int)p[(size_t)E + i];
    } else {
        const int* p = (const int*)ei;
        s = p[i]; d = p[E + i];
    }
}

__device__ __forceinline__ float lrelu_exp(float v) {
    v = v > 0.f ? v : NEG * v;
    return __expf(v);
}

#define FMA2(acc, a2, w2) \
    asm("fma.rn.f32x2 %0, %1, %2, %0;" : "+l"(acc) : "l"(a2), "l"(w2))

// ============ KZ: dtype probe + zero counts ============
__global__ void kz(const int* ei32, int E, int n) {
    int i = blockIdx.x * 1024 + threadIdx.x;
    if (i <= n) g_cnt[i] = 0;
    if (blockIdx.x == 0) {
        __shared__ int flag;
        if (threadIdx.x == 0) flag = 0;
        __syncthreads();
        for (int j = threadIdx.x; j < 2048; j += 1024) {
            int idx = 2 * j + 1;
            if (idx < 2 * E && ei32[idx] != 0) flag = 1;
        }
        __syncthreads();
        if (threadIdx.x == 0) g_is64 = (flag == 0);
    }
}

// ============ KC2: count in-degrees ============
__global__ void kc2_count(const void* __restrict__ ei, int E) {
    int i = blockIdx.x * blockDim.x + threadIdx.x;
    if (i >= E) return;
    int s, d; load_edge(ei, E, i, s, d);
    atomicAdd(&g_cnt[d], 1);
}

// ============ KV: attention-vector precomputes ============
__global__ void kv(const float* __restrict__ W1, const float* __restrict__ a_s1,
                   const float* __restrict__ a_d1, const float* __restrict__ W2,
                   const float* __restrict__ a_s2, const float* __restrict__ a_d2) {
    int t = blockIdx.x * 256 + threadIdx.x;
    if (t < NF * 8) {
        int k = t >> 3, o = t & 7, h = o & 3;
        const float* a = (o < 4 ? a_s1 : a_d1) + h * 64;
        const float* w = W1 + (size_t)k * HH + h * 64;
        float s = 0.f;
        #pragma unroll 8
        for (int c = 0; c < 64; c++) s += w[c] * a[c];
        g_va1[t] = s;
    } else if (t < NF * 8 + HH * 2) {
        int q = t - NF * 8;
        int k = q >> 1, o = q & 1;
        const float* a = o ? a_d2 : a_s2;
        const float* w = W2 + (size_t)k * OUT2;
        float s = 0.f;
        #pragma unroll 8
        for (int c = 0; c < OUT2; c++) s += w[c] * a[c];
        g_wa2[q] = s;
    }
}

// ============ K1: h1 = x @ W1 (dup-operand f32x2) + layer-1 logits ============
__global__ void k1_gemm1(const float* __restrict__ x, const float* __restrict__ W1,
                         int n_nodes) {
    __shared__ float xs2[32][2 * NF + 4];   // duplicated k-pairs, stride 260 (33 KB)
    __shared__ float sva[NF * 8];           // 4 KB
    const int n0 = blockIdx.x * 32;
    const int tid = threadIdx.x;            // 256
    for (int i = tid; i < NF * 8; i += 256) sva[i] = g_va1[i];
    #pragma unroll
    for (int r = 0; r < 4; r++) {
        int i = tid + r * 256;              // 1024 tasks: 32 nodes x 32 float4s
        int nn = i >> 5, k4 = i & 31;
        int g = n0 + nn;
        float4 v = make_float4(0.f, 0.f, 0.f, 0.f);
        if (g < n_nodes) v = *reinterpret_cast<const float4*>(x + (size_t)g * NF + 4 * k4);
        float4 lo = make_float4(v.x, v.x, v.y, v.y);
        float4 hi = make_float4(v.z, v.z, v.w, v.w);
        *reinterpret_cast<float4*>(&xs2[nn][8 * k4])     = lo;
        *reinterpret_cast<float4*>(&xs2[nn][8 * k4 + 4]) = hi;
    }
    __syncthreads();
    const int tx = tid & 63, ty = tid >> 6;  // cols 4tx..4tx+3, nodes ty*8+t
    unsigned long long acc[8][2] = {};
    const float* wp = W1 + 4 * tx;
    #pragma unroll 2
    for (int k2 = 0; k2 < NF; k2 += 2) {
        ulonglong2 wa = *reinterpret_cast<const ulonglong2*>(wp + (size_t)k2 * HH);
        ulonglong2 wb = *reinterpret_cast<const ulonglong2*>(wp + (size_t)(k2 + 1) * HH);
        #pragma unroll
        for (int t = 0; t < 8; t++) {
            ulonglong2 ap = *reinterpret_cast<const ulonglong2*>(&xs2[ty * 8 + t][2 * k2]);
            FMA2(acc[t][0], ap.x, wa.x);
            FMA2(acc[t][1], ap.x, wa.y);
            FMA2(acc[t][0], ap.y, wb.x);
            FMA2(acc[t][1], ap.y, wb.y);
        }
    }
    #pragma unroll
    for (int t = 0; t < 8; t++) {
        int g = n0 + ty * 8 + t;
        if (g < n_nodes) {
            float4 o;
            o.x = __uint_as_float((unsigned)(acc[t][0]));
            o.y = __uint_as_float((unsigned)(acc[t][0] >> 32));
            o.z = __uint_as_float((unsigned)(acc[t][1]));
            o.w = __uint_as_float((unsigned)(acc[t][1] >> 32));
            *reinterpret_cast<float4*>(g_h1 + (size_t)g * HH + 4 * tx) = o;
        }
    }
    // fused layer-1 logits: 256 threads = 32 nodes x 8 outputs
    {
        int nn = tid >> 3, o = tid & 7;
        int g = n0 + nn;
        float s = 0.f;
        #pragma unroll 8
        for (int k = 0; k < NF; k++) s += xs2[nn][2 * k] * sva[k * 8 + o];
        if (g < n_nodes) {
            if (o < 4) g_as1[g * 4 + o] = s;
            else       g_ad1[g * 4 + o - 4] = s;
        }
    }
}

// ============ scan ============
__global__ void s1_scan(int n) {
    __shared__ int sd[1024];
    int tid = threadIdx.x;
    int i = blockIdx.x * 1024 + tid;
    int v = (i < n) ? g_cnt[i] : 0;
    sd[tid] = v;
    __syncthreads();
    #pragma unroll
    for (int off = 1; off < 1024; off <<= 1) {
        int t = (tid >= off) ? sd[tid - off] : 0;
        __syncthreads();
        sd[tid] += t;
        __syncthreads();
    }
    if (i < n) g_off[i] = sd[tid] - v;
    if (tid == 1023) g_bsum[blockIdx.x] = sd[1023];
}
__global__ void s2_scan(int nb) {
    if (threadIdx.x == 0) {
        int acc = 0;
        for (int b = 0; b < nb; b++) { int t = g_bsum[b]; g_boff[b] = acc; acc += t; }
    }
}
__global__ void s3_scan(int n, int E) {
    int i = blockIdx.x * 1024 + threadIdx.x;
    if (i < n) {
        int v = g_off[i] + g_boff[blockIdx.x];
        g_off[i] = v;
        g_cur[i] = v;
    }
    if (i == 0) g_off[n] = E;
}

// ============ KC3W1: CSR fill + layer-1 softmax numerators ============
__global__ void kc3w1(const void* __restrict__ ei, int E) {
    int i = blockIdx.x * blockDim.x + threadIdx.x;
    if (i >= E) return;
    int s, d; load_edge(ei, E, i, s, d);
    int p = atomicAdd(&g_cur[d], 1);
    g_csrc[p] = s;
    float4 as = *reinterpret_cast<const float4*>(g_as1 + 4 * s);
    float4 ad = *reinterpret_cast<const float4*>(g_ad1 + 4 * d);
    float4 w;
    w.x = lrelu_exp(as.x + ad.x);
    w.y = lrelu_exp(as.y + ad.y);
    w.z = lrelu_exp(as.z + ad.z);
    w.w = lrelu_exp(as.w + ad.w);
    *reinterpret_cast<float4*>(g_w1 + (size_t)p * 4) = w;
}

// ============ KA1: gather aggregation, layer 1 (smem-staged edges) ============
__global__ void ka1(int n_nodes) {
    __shared__ int   ssrc[128];
    __shared__ float sw[128 * 4];
    const int d = blockIdx.x;
    const int j = threadIdx.x;    // 256
    const int h = j >> 6;
    float w0 = lrelu_exp(g_as1[d * NHEADS + h] + g_ad1[d * NHEADS + h]);
    float den = w0;
    float acc = w0 * g_h1[(size_t)d * HH + j];
    const int pB = g_off[d], pE = g_off[d + 1];
    for (int p0 = pB; p0 < pE; p0 += 128) {
        int np = min(128, pE - p0);
        __syncthreads();
        if (j < np) {
            ssrc[j] = g_csrc[p0 + j];
        } else if (j >= 128 && j - 128 < np) {
            int e = j - 128;
            *reinterpret_cast<float4*>(&sw[4 * e]) =
                *reinterpret_cast<const float4*>(g_w1 + (size_t)(p0 + e) * 4);
        }
        __syncthreads();
        #pragma unroll 4
        for (int e = 0; e < np; e++) {
            int s = ssrc[e];
            float wp = sw[4 * e + h];
            den += wp;
            acc += wp * g_h1[(size_t)s * HH + j];
        }
    }
    g_agg1[(size_t)d * HH + j] = acc / den;
}

// ============ K4: h2 = elu(agg1+b1) @ W2 (dup-operand f32x2, 2 k-halves) ============
__global__ void k4_gemm2(const float* __restrict__ W2, const float* __restrict__ b1,
                         int n_nodes) {
    __shared__ float xs2[32][2 * 128 + 4];  // one k-half duplicated, 33 KB
    __shared__ float swa[HH * 2];           // 2 KB
    const int n0 = blockIdx.x * 32;
    const int tid = threadIdx.x;            // 256
    for (int i = tid; i < HH * 2; i += 256) swa[i] = g_wa2[i];
    const int tx = tid & 31, ty = tid >> 5; // cols 4tx..4tx+3, nodes ty*4+t
    unsigned long long acc[4][2] = {};
    float ls = 0.f;                         // partial logit (tid<64)
    #pragma unroll
    for (int half = 0; half < 2; half++) {
        const int kbase = half * 128;
        __syncthreads();
        #pragma unroll
        for (int r = 0; r < 4; r++) {
            int i = tid + r * 256;          // 1024 tasks: 32 nodes x 32 float4s
            int nn = i >> 5, k4 = i & 31;
            int g = n0 + nn;
            float4 v = make_float4(0.f, 0.f, 0.f, 0.f);
            if (g < n_nodes) {
                int kk = kbase + 4 * k4;
                v = *reinterpret_cast<const float4*>(g_agg1 + (size_t)g * HH + kk);
                float4 b = *reinterpret_cast<const float4*>(b1 + kk);
                v.x += b.x; v.y += b.y; v.z += b.z; v.w += b.w;
                v.x = v.x > 0.f ? v.x : expm1f(v.x);
                v.y = v.y > 0.f ? v.y : expm1f(v.y);
                v.z = v.z > 0.f ? v.z : expm1f(v.z);
                v.w = v.w > 0.f ? v.w : expm1f(v.w);
            }
            float4 lo = make_float4(v.x, v.x, v.y, v.y);
            float4 hi = make_float4(v.z, v.z, v.w, v.w);
            *reinterpret_cast<float4*>(&xs2[nn][8 * k4])     = lo;
            *reinterpret_cast<float4*>(&xs2[nn][8 * k4 + 4]) = hi;
        }
        __syncthreads();
        const float* wp = W2 + (size_t)kbase * OUT2 + 4 * tx;
        #pragma unroll 2
        for (int k2 = 0; k2 < 128; k2 += 2) {
            ulonglong2 wa = *reinterpret_cast<const ulonglong2*>(wp + (size_t)k2 * OUT2);
            ulonglong2 wb = *reinterpret_cast<const ulonglong2*>(wp + (size_t)(k2 + 1) * OUT2);
            #pragma unroll
            for (int t = 0; t < 4; t++) {
                ulonglong2 ap = *reinterpret_cast<const ulonglong2*>(&xs2[ty * 4 + t][2 * k2]);
                FMA2(acc[t][0], ap.x, wa.x);
                FMA2(acc[t][1], ap.x, wa.y);
                FMA2(acc[t][0], ap.y, wb.x);
                FMA2(acc[t][1], ap.y, wb.y);
            }
        }
        if (tid < 64) {
            int nn = tid >> 1, o = tid & 1;
            #pragma unroll 8
            for (int k = 0; k < 128; k++)
                ls += xs2[nn][2 * k] * swa[2 * (kbase + k) + o];
        }
    }
    #pragma unroll
    for (int t = 0; t < 4; t++) {
        int g = n0 + ty * 4 + t;
        if (g < n_nodes) {
            float4 o;
            o.x = __uint_as_float((unsigned)(acc[t][0]));
            o.y = __uint_as_float((unsigned)(acc[t][0] >> 32));
            o.z = __uint_as_float((unsigned)(acc[t][1]));
            o.w = __uint_as_float((unsigned)(acc[t][1] >> 32));
            *reinterpret_cast<float4*>(g_h2 + (size_t)g * OUT2 + 4 * tx) = o;
        }
    }
    if (tid < 64) {
        int nn = tid >> 1, o = tid & 1;
        int g = n0 + nn;
        if (g < n_nodes) {
            if (o == 0) g_as2[g] = ls;
            else        g_ad2[g] = ls;
        }
    }
}

// ============ KA2: gather aggregation, layer 2 ============
__global__ void ka2(int n_nodes, const float* __restrict__ b2,
                    float* __restrict__ out) {
    __shared__ int   ssrc[128];
    __shared__ float sw[128];
    const int d = blockIdx.x;
    const int j = threadIdx.x;   // 128
    float add = g_ad2[d];
    float w0 = lrelu_exp(g_as2[d] + add);
    float den = w0;
    float acc = w0 * g_h2[(size_t)d * OUT2 + j];
    const int pB = g_off[d], pE = g_off[d + 1];
    for (int p0 = pB; p0 < pE; p0 += 128) {
        int np = min(128, pE - p0);
        __syncthreads();
        if (j < np) {
            int s = g_csrc[p0 + j];
            ssrc[j] = s;
            sw[j] = lrelu_exp(g_as2[s] + add);
        }
        __syncthreads();
        #pragma unroll 4
        for (int e = 0; e < np; e++) {
            int s = ssrc[e];
            float wp = sw[e];
            den += wp;
            acc += wp * g_h2[(size_t)s * OUT2 + j];
        }
    }
    out[(size_t)d * OUT2 + j] = acc / den + b2[j];
}

extern "C" void kernel_launch(void* const* d_in, const int* in_sizes, int n_in,
                              void* d_out, int out_size) {
    const float* x    = (const float*)d_in[0];
    const void*  ei   = d_in[1];
    const float* W1   = (const float*)d_in[2];
    const float* as1  = (const float*)d_in[3];
    const float* ad1  = (const float*)d_in[4];
    const float* b1   = (const float*)d_in[5];
    const float* W2   = (const float*)d_in[6];
    const float* as2  = (const float*)d_in[7];
    const float* ad2  = (const float*)d_in[8];
    const float* b2   = (const float*)d_in[9];
    float* out = (float*)d_out;

    const int n_nodes = in_sizes[0] / NF;
    const int E  = in_sizes[1] / 2;

    const int gemm_blocks = (n_nodes + 31) / 32;
    const int eb = (E + 255) / 256;
    const int nb = (n_nodes + 1023) / 1024;

    kz<<<nb + 1, 1024>>>((const int*)ei, E, n_nodes);          // 1
    kc2_count<<<eb, 256>>>(ei, E);                             // 2
    kv<<<6, 256>>>(W1, as1, ad1, W2, as2, ad2);                // 3
    k1_gemm1<<<gemm_blocks, 256>>>(x, W1, n_nodes);            // 4  <- profiled slot
    s1_scan<<<nb, 1024>>>(n_nodes);                            // 5
    s2_scan<<<1, 32>>>(nb);                                    // 6
    s3_scan<<<nb, 1024>>>(n_nodes, E);                         // 7
    kc3w1<<<eb, 256>>>(ei, E);                                 // 8
    ka1<<<n_nodes, 256>>>(n_nodes);                            // 9
    k4_gemm2<<<gemm_blocks, 256>>>(W2, b1, n_nodes);           // 10
    ka2<<<n_nodes, 128>>>(n_nodes, b2, out);                   // 11
}